// round 6
// baseline (speedup 1.0000x reference)
#include <cuda_runtime.h>
#include <stdint.h>

// z[e, :] = h[src[e], :] * h[dst[e], :]
// h: [N=50000, D=64] fp32 (12.8 MB, L2-resident), src/dst: [E=800000] int32,
// out: [E, 64] fp32.
// R5 lesson: more MLP = neutral; L1tex (74.7%) dominated by the gather MISS
// path (fills into L1 data array that are never reused, hit rate ~1.8%).
// R6: gathers use ld.global.nc.L1::no_allocate -> no L1 fill/evict work,
// straight L2->regs. Index loads stay cached; stores stay streaming (.cs).

static constexpr int D = 64;
static constexpr int VEC_PER_ROW = D / 4;   // 16 float4 per row

__device__ __forceinline__ float4 ldg_bypass_l1(const float4* p) {
    float4 v;
    asm volatile("ld.global.nc.L1::no_allocate.v4.f32 {%0,%1,%2,%3}, [%4];"
                 : "=f"(v.x), "=f"(v.y), "=f"(v.z), "=f"(v.w)
                 : "l"(p));
    return v;
}

__global__ void __launch_bounds__(256, 8) u_mul_v_kernel(
    const float4* __restrict__ h,        // [N, 16] as float4
    const int* __restrict__ src,         // [E] int32
    const int* __restrict__ dst,         // [E] int32
    float4* __restrict__ out,            // [E, 16] as float4
    int n_edges,
    int half)                            // ceil(E/2)
{
    const int t = blockIdx.x * 256 + threadIdx.x;
    const int p = t >> 3;                // pair id
    const int j = t & 7;                 // float4 slot within row half
    if (p >= half) return;

    const int e0 = p;
    const int e1 = p + half;
    const bool has_e1 = (e1 < n_edges);

    // 8 adjacent threads share each index -> L1 broadcast (keep cached).
    const int s0 = __ldg(&src[e0]);
    const int d0 = __ldg(&dst[e0]);
    const int s1 = has_e1 ? __ldg(&src[e1]) : 0;
    const int d1 = has_e1 ? __ldg(&dst[e1]) : 0;

    const float4* hs0 = h + (size_t)s0 * VEC_PER_ROW;
    const float4* hd0 = h + (size_t)d0 * VEC_PER_ROW;
    const float4* hs1 = h + (size_t)s1 * VEC_PER_ROW;
    const float4* hd1 = h + (size_t)d1 * VEC_PER_ROW;

    // Issue all 8 gathers up front; none allocate in L1.
    const float4 a0 = ldg_bypass_l1(hs0 + j);
    const float4 b0 = ldg_bypass_l1(hd0 + j);
    const float4 a1 = ldg_bypass_l1(hs0 + j + 8);
    const float4 b1 = ldg_bypass_l1(hd0 + j + 8);
    const float4 c0 = ldg_bypass_l1(hs1 + j);
    const float4 g0 = ldg_bypass_l1(hd1 + j);
    const float4 c1 = ldg_bypass_l1(hs1 + j + 8);
    const float4 g1 = ldg_bypass_l1(hd1 + j + 8);

    float4 r0, r1;
    r0.x = a0.x * b0.x; r0.y = a0.y * b0.y;
    r0.z = a0.z * b0.z; r0.w = a0.w * b0.w;
    r1.x = a1.x * b1.x; r1.y = a1.y * b1.y;
    r1.z = a1.z * b1.z; r1.w = a1.w * b1.w;

    float4* o0 = out + (size_t)e0 * VEC_PER_ROW + j;
    __stcs(o0, r0);
    __stcs(o0 + 8, r1);

    if (has_e1) {
        float4 q0, q1;
        q0.x = c0.x * g0.x; q0.y = c0.y * g0.y;
        q0.z = c0.z * g0.z; q0.w = c0.w * g0.w;
        q1.x = c1.x * g1.x; q1.y = c1.y * g1.y;
        q1.z = c1.z * g1.z; q1.w = c1.w * g1.w;

        float4* o1 = out + (size_t)e1 * VEC_PER_ROW + j;
        __stcs(o1, q0);
        __stcs(o1 + 8, q1);
    }
}

extern "C" void kernel_launch(void* const* d_in, const int* in_sizes, int n_in,
                              void* d_out, int out_size) {
    const float4* h = (const float4*)d_in[0];
    const int* src = (const int*)d_in[1];
    const int* dst = (const int*)d_in[2];
    float4* out = (float4*)d_out;

    const int n_edges = in_sizes[1];          // E = 800000
    const int half = (n_edges + 1) / 2;       // 400000
    const long long total = (long long)half * 8;
    const int threads = 256;
    const int blocks = (int)((total + threads - 1) / threads);

    u_mul_v_kernel<<<blocks, threads>>>(h, src, dst, out, n_edges, half);
}

// round 7
// speedup vs baseline: 1.0158x; 1.0158x over previous
#include <cuda_runtime.h>
#include <stdint.h>

// z[e, :] = h[src[e], :] * h[dst[e], :]
// h: [N=50000, D=64] fp32 (12.8 MB, L2-resident), src/dst: [E=800000] int32,
// out: [E, 64] fp32.
// R6 lesson: L1 bypass neutral; profile invariant across MLP/policy changes.
// R7 experiment: 4 edges/thread (16 outstanding gather LDG.128, ~90 regs,
// ~25-30% occ) to disambiguate queue-limited gathers vs DRAM write-drain.
// 8 threads/edge keeps every warp load = 4 full 128B lines; stores coalesced.

static constexpr int D = 64;
static constexpr int VEC_PER_ROW = D / 4;   // 16 float4 per row
static constexpr int EPT = 4;               // edges per thread

__global__ void __launch_bounds__(256) u_mul_v_kernel(
    const float4* __restrict__ h,        // [N, 16] as float4
    const int* __restrict__ src,         // [E] int32
    const int* __restrict__ dst,         // [E] int32
    float4* __restrict__ out,            // [E, 16] as float4
    int n_edges,
    int quarter)                         // ceil(E/4)
{
    const int t = blockIdx.x * 256 + threadIdx.x;
    const int p = t >> 3;                // edge-group id
    const int j = t & 7;                 // float4 slot within row half
    if (p >= quarter) return;

    int e[EPT];
    bool ok[EPT];
    const float4* hs[EPT];
    const float4* hd[EPT];

#pragma unroll
    for (int k = 0; k < EPT; k++) {
        e[k] = p + k * quarter;
        ok[k] = (e[k] < n_edges);
        const int s = ok[k] ? __ldg(&src[e[k]]) : 0;
        const int d = ok[k] ? __ldg(&dst[e[k]]) : 0;
        hs[k] = h + (size_t)s * VEC_PER_ROW;
        hd[k] = h + (size_t)d * VEC_PER_ROW;
    }

    // Front-batch all 16 gathers for maximum outstanding misses.
    float4 a0[EPT], b0[EPT], a1[EPT], b1[EPT];
#pragma unroll
    for (int k = 0; k < EPT; k++) {
        a0[k] = __ldg(hs[k] + j);
        b0[k] = __ldg(hd[k] + j);
        a1[k] = __ldg(hs[k] + j + 8);
        b1[k] = __ldg(hd[k] + j + 8);
    }

#pragma unroll
    for (int k = 0; k < EPT; k++) {
        if (!ok[k]) continue;
        float4 r0, r1;
        r0.x = a0[k].x * b0[k].x; r0.y = a0[k].y * b0[k].y;
        r0.z = a0[k].z * b0[k].z; r0.w = a0[k].w * b0[k].w;
        r1.x = a1[k].x * b1[k].x; r1.y = a1[k].y * b1[k].y;
        r1.z = a1[k].z * b1[k].z; r1.w = a1[k].w * b1[k].w;

        float4* o = out + (size_t)e[k] * VEC_PER_ROW + j;
        __stcs(o, r0);          // streaming: don't evict h from L2
        __stcs(o + 8, r1);
    }
}

extern "C" void kernel_launch(void* const* d_in, const int* in_sizes, int n_in,
                              void* d_out, int out_size) {
    const float4* h = (const float4*)d_in[0];
    const int* src = (const int*)d_in[1];
    const int* dst = (const int*)d_in[2];
    float4* out = (float4*)d_out;

    const int n_edges = in_sizes[1];            // E = 800000
    const int quarter = (n_edges + 3) / 4;      // 200000
    const long long total = (long long)quarter * 8;
    const int threads = 256;
    const int blocks = (int)((total + threads - 1) / threads);

    u_mul_v_kernel<<<blocks, threads>>>(h, src, dst, out, n_edges, quarter);
}